// round 2
// baseline (speedup 1.0000x reference)
#include <cuda_runtime.h>
#include <mma.h>
#include <math.h>
#include <stdint.h>

using namespace nvcuda;

// Problem constants
#define T_LEN   4096
#define B_SZ    32
#define D_MODEL 256
#define H_DIM   512
#define KFREQ   128
#define LN_EPS  1e-5f

// ---------------- device scratch (no allocations allowed) ----------------
__device__ float g_lutc[T_LEN];          // cos(2*pi*n/T)
__device__ float g_luts[T_LEN];          // sin(2*pi*n/T)
__device__ float g_ren[B_SZ * KFREQ];    // Re(X)/|X|  = cos(phase0)
__device__ float g_imn[B_SZ * KFREQ];    // Im(X)/|X|  = sin(phase0)
__device__ float g_base[B_SZ * H_DIM];   // mag @ w1[:128,:] + b1  (t-independent)

// ---------------- kernel 0: twiddle LUT ----------------
__global__ void lut_kernel() {
    int i = blockIdx.x * blockDim.x + threadIdx.x;
    if (i < T_LEN) {
        // 2*pi/4096 in double, then sincos in float (arg < 2*pi, well conditioned)
        float ph = (float)((double)i * 1.5339807878856412e-3);
        float s, c;
        sincosf(ph, &s, &c);
        g_lutc[i] = c;
        g_luts[i] = s;
    }
}

// ---------------- kernel 1: DFT bins + normalized phase + base ----------------
// grid = 32 (one block per batch), block = 256 threads
// dyn smem: sig[4096] + lc[4096] + ls[4096] + mag[128]
#define SPEC_SMEM_FLOATS (T_LEN * 3 + KFREQ)
__global__ __launch_bounds__(256) void spectral_kernel(
    const int* __restrict__ byte_ids,
    const float* __restrict__ freq_bands,
    const float* __restrict__ w1,
    const float* __restrict__ b1)
{
    extern __shared__ float sm[];
    float* sig  = sm;
    float* lc   = sm + T_LEN;
    float* ls   = sm + 2 * T_LEN;
    float* magS = sm + 3 * T_LEN;

    int b   = blockIdx.x;
    int tid = threadIdx.x;

    for (int i = tid; i < T_LEN; i += 256) {
        sig[i] = (float)byte_ids[b * T_LEN + i] * (1.0f / 127.5f) - 1.0f;
        lc[i]  = g_lutc[i];
        ls[i]  = g_luts[i];
    }
    __syncthreads();

    int warp = tid >> 5, lane = tid & 31;
    for (int f = warp; f < KFREQ; f += 8) {
        float cacc = 0.f, sacc = 0.f;
        int idx  = (lane * f) & (T_LEN - 1);
        int step = (32 * f) & (T_LEN - 1);
        for (int i = lane; i < T_LEN; i += 32) {
            float sv = sig[i];
            cacc += sv * lc[idx];
            sacc += sv * ls[idx];
            idx = (idx + step) & (T_LEN - 1);
        }
        #pragma unroll
        for (int o = 16; o; o >>= 1) {
            cacc += __shfl_xor_sync(0xffffffffu, cacc, o);
            sacc += __shfl_xor_sync(0xffffffffu, sacc, o);
        }
        if (lane == 0) {
            // FFT convention: X = sum x * exp(-i*2pi*t*f/T) => Re=cacc, Im=-sacc
            float re = cacc, im = -sacc;
            float hyp = sqrtf(re * re + im * im);
            float rn, in_;
            if (hyp > 1e-30f) {
                float inv = 1.0f / hyp;
                rn = re * inv; in_ = im * inv;
            } else {
                rn = 1.0f; in_ = 0.0f;  // angle(0) = 0
            }
            g_ren[b * KFREQ + f] = rn;
            g_imn[b * KFREQ + f] = in_;
            magS[f] = hyp * freq_bands[f];
        }
    }
    __syncthreads();

    // base[b, j] = b1[j] + sum_f mag[f] * w1[f, j]   (w1 rows 0..127)
    for (int j = tid; j < H_DIM; j += 256) {
        float acc = b1[j];
        for (int f = 0; f < KFREQ; f++)
            acc += magS[f] * w1[f * H_DIM + j];
        g_base[b * H_DIM + j] = acc;
    }
}

// ---------------- kernel 2: fused  A@W1b -> +base -> LN -> GELU -> @W2 -> +b2 ----------------
// A[t, f] = imn[f]*cos(2pi t f/T) + ren[f]*sin(2pi t f/T)   (the sin(phase) features)
// grid = 2048 (32 batches * 64 row-tiles of 64), block = 512 threads (16 warps)
// warp grid: wm in {0,1} (rows 32*wm..), wn in {0..7}
// dyn smem layout (floats):
//   hsm  [64*520]            row-major h / g / C2 staging, ld=520
//   B1s  [8*516]             GEMM1 B chunk (ld=516); B2 chunk overlaps (8*260, ld=260)
//   A1s  [64*12]             GEMM1 A chunk (ld=12)
//   imnS[128], renS[128]
//   lc[4096], ls[4096]
#define HSM_LD   520
#define B1_LD    516
#define B2_LD    260
#define A1_LD    12
#define OFF_HSM  0
#define OFF_B1   (64 * HSM_LD)
#define OFF_A1   (OFF_B1 + 8 * B1_LD)
#define OFF_IMN  (OFF_A1 + 64 * A1_LD)
#define OFF_REN  (OFF_IMN + KFREQ)
#define OFF_LC   (OFF_REN + KFREQ)
#define OFF_LS   (OFF_LC + T_LEN)
#define FUSED_SMEM_FLOATS (OFF_LS + T_LEN)

__global__ __launch_bounds__(512, 1) void fused_kernel(
    const float* __restrict__ w1,
    const float* __restrict__ w2,
    const float* __restrict__ gamma,
    const float* __restrict__ beta,
    const float* __restrict__ b2v,
    float* __restrict__ out)
{
    extern __shared__ float sm[];
    float* hsm  = sm + OFF_HSM;
    float* B1s  = sm + OFF_B1;   // also B2s
    float* A1s  = sm + OFF_A1;
    float* imnS = sm + OFF_IMN;
    float* renS = sm + OFF_REN;
    float* lc   = sm + OFF_LC;
    float* ls   = sm + OFF_LS;

    int tid = threadIdx.x;
    int blk = blockIdx.x;
    int b   = blk >> 6;
    int t0  = (blk & 63) * 64;

    for (int i = tid; i < T_LEN; i += 512) { lc[i] = g_lutc[i]; ls[i] = g_luts[i]; }
    if (tid < KFREQ) {
        imnS[tid] = g_imn[b * KFREQ + tid];
        renS[tid] = g_ren[b * KFREQ + tid];
    }
    __syncthreads();

    int warp = tid >> 5, lane = tid & 31;
    int wm = warp >> 3, wn = warp & 7;

    // ---------------- GEMM1: C1(64x512) = A(64x128) @ W1b(128x512) ----------------
    wmma::fragment<wmma::accumulator, 16, 16, 8, float> c1[2][4];
    #pragma unroll
    for (int im = 0; im < 2; im++)
        #pragma unroll
        for (int jn = 0; jn < 4; jn++)
            wmma::fill_fragment(c1[im][jn], 0.0f);

    int ar = tid >> 3, af = tid & 7;  // this thread's A element (row, col-in-chunk)
    float breg[8];
    float aval;

    // prefetch chunk 0
    {
        int f0 = 0;
        #pragma unroll
        for (int i = 0; i < 8; i++) breg[i] = w1[(KFREQ + f0 + i) * H_DIM + tid];
        int f = f0 + af, t = t0 + ar;
        int idx = (t * f) & (T_LEN - 1);
        aval = imnS[f] * lc[idx] + renS[f] * ls[idx];
    }

    for (int kc = 0; kc < 16; kc++) {
        __syncthreads();
        #pragma unroll
        for (int i = 0; i < 8; i++) B1s[i * B1_LD + tid] = wmma::__float_to_tf32(breg[i]);
        A1s[ar * A1_LD + af] = wmma::__float_to_tf32(aval);
        __syncthreads();
        if (kc < 15) {  // prefetch next chunk (overlaps with MMA below)
            int f0 = (kc + 1) * 8;
            #pragma unroll
            for (int i = 0; i < 8; i++) breg[i] = w1[(KFREQ + f0 + i) * H_DIM + tid];
            int f = f0 + af, t = t0 + ar;
            int idx = (t * f) & (T_LEN - 1);
            aval = imnS[f] * lc[idx] + renS[f] * ls[idx];
        }
        wmma::fragment<wmma::matrix_a, 16, 16, 8, wmma::precision::tf32, wmma::row_major> afr[2];
        #pragma unroll
        for (int im = 0; im < 2; im++)
            wmma::load_matrix_sync(afr[im], A1s + (32 * wm + 16 * im) * A1_LD, A1_LD);
        #pragma unroll
        for (int jn = 0; jn < 4; jn++) {
            wmma::fragment<wmma::matrix_b, 16, 16, 8, wmma::precision::tf32, wmma::row_major> bfr;
            wmma::load_matrix_sync(bfr, B1s + 64 * wn + 16 * jn, B1_LD);
            #pragma unroll
            for (int im = 0; im < 2; im++)
                wmma::mma_sync(c1[im][jn], afr[im], bfr, c1[im][jn]);
        }
    }

    // store C1 tiles into hsm
    #pragma unroll
    for (int im = 0; im < 2; im++)
        #pragma unroll
        for (int jn = 0; jn < 4; jn++)
            wmma::store_matrix_sync(hsm + (32 * wm + 16 * im) * HSM_LD + 64 * wn + 16 * jn,
                                    c1[im][jn], HSM_LD, wmma::mem_row_major);
    __syncthreads();

    // ---------------- LayerNorm + exact GELU (rows 4*warp .. 4*warp+3) ----------------
    {
        const float* baseP = g_base + b * H_DIM;
        for (int rr = 0; rr < 4; rr++) {
            int r = warp * 4 + rr;
            float x[16];
            float s1 = 0.f, s2 = 0.f;
            #pragma unroll
            for (int q = 0; q < 16; q++) {
                int j = q * 32 + lane;
                float v = hsm[r * HSM_LD + j] + baseP[j];
                x[q] = v; s1 += v; s2 += v * v;
            }
            #pragma unroll
            for (int o = 16; o; o >>= 1) {
                s1 += __shfl_xor_sync(0xffffffffu, s1, o);
                s2 += __shfl_xor_sync(0xffffffffu, s2, o);
            }
            float mean = s1 * (1.0f / H_DIM);
            float var  = s2 * (1.0f / H_DIM) - mean * mean;
            float rstd = rsqrtf(var + LN_EPS);
            #pragma unroll
            for (int q = 0; q < 16; q++) {
                int j = q * 32 + lane;
                float y = (x[q] - mean) * rstd * gamma[j] + beta[j];
                float g = 0.5f * y * (1.0f + erff(y * 0.70710678118654752f));
                hsm[r * HSM_LD + j] = wmma::__float_to_tf32(g);
            }
        }
    }
    __syncthreads();

    // ---------------- GEMM2: C2(64x256) = g(64x512) @ W2(512x256) ----------------
    wmma::fragment<wmma::accumulator, 16, 16, 8, float> c2[2][2];
    #pragma unroll
    for (int im = 0; im < 2; im++)
        #pragma unroll
        for (int jn = 0; jn < 2; jn++)
            wmma::fill_fragment(c2[im][jn], 0.0f);

    float* B2s = B1s;
    int j2 = tid & 255, i0 = tid >> 8;   // each thread loads rows {i0, i0+2, i0+4, i0+6}, column j2
    float breg2[4];
    {
        #pragma unroll
        for (int i = 0; i < 4; i++) breg2[i] = w2[(0 * 8 + i0 + 2 * i) * D_MODEL + j2];
    }
    for (int kc = 0; kc < 64; kc++) {
        __syncthreads();
        #pragma unroll
        for (int i = 0; i < 4; i++)
            B2s[(i0 + 2 * i) * B2_LD + j2] = wmma::__float_to_tf32(breg2[i]);
        __syncthreads();
        if (kc < 63) {
            #pragma unroll
            for (int i = 0; i < 4; i++)
                breg2[i] = w2[((kc + 1) * 8 + i0 + 2 * i) * D_MODEL + j2];
        }
        wmma::fragment<wmma::matrix_a, 16, 16, 8, wmma::precision::tf32, wmma::row_major> a2[2];
        #pragma unroll
        for (int im = 0; im < 2; im++)
            wmma::load_matrix_sync(a2[im], hsm + (32 * wm + 16 * im) * HSM_LD + kc * 8, HSM_LD);
        #pragma unroll
        for (int jn = 0; jn < 2; jn++) {
            wmma::fragment<wmma::matrix_b, 16, 16, 8, wmma::precision::tf32, wmma::row_major> b2fr;
            wmma::load_matrix_sync(b2fr, B2s + 32 * wn + 16 * jn, B2_LD);
            #pragma unroll
            for (int im = 0; im < 2; im++)
                wmma::mma_sync(c2[im][jn], a2[im], b2fr, c2[im][jn]);
        }
    }
    __syncthreads();

    // stage C2 into hsm (cols 0..255), then epilogue +b2 -> gmem
    #pragma unroll
    for (int im = 0; im < 2; im++)
        #pragma unroll
        for (int jn = 0; jn < 2; jn++)
            wmma::store_matrix_sync(hsm + (32 * wm + 16 * im) * HSM_LD + 32 * wn + 16 * jn,
                                    c2[im][jn], HSM_LD, wmma::mem_row_major);
    __syncthreads();

    for (int e = tid; e < 64 * D_MODEL; e += 512) {
        int r = e >> 8, j = e & 255;
        out[(size_t)(b * T_LEN + t0 + r) * D_MODEL + j] = hsm[r * HSM_LD + j] + b2v[j];
    }
}

// ---------------- launch ----------------
extern "C" void kernel_launch(void* const* d_in, const int* in_sizes, int n_in,
                              void* d_out, int out_size) {
    const int*   byte_ids = (const int*)  d_in[0];
    const float* fb       = (const float*)d_in[1];
    const float* w1       = (const float*)d_in[2];
    const float* b1       = (const float*)d_in[3];
    const float* gamma    = (const float*)d_in[4];
    const float* beta     = (const float*)d_in[5];
    const float* w2       = (const float*)d_in[6];
    const float* b2v      = (const float*)d_in[7];
    float* out = (float*)d_out;

    (void)in_sizes; (void)n_in; (void)out_size;

    cudaFuncSetAttribute(spectral_kernel, cudaFuncAttributeMaxDynamicSharedMemorySize,
                         SPEC_SMEM_FLOATS * (int)sizeof(float));
    cudaFuncSetAttribute(fused_kernel, cudaFuncAttributeMaxDynamicSharedMemorySize,
                         FUSED_SMEM_FLOATS * (int)sizeof(float));

    lut_kernel<<<(T_LEN + 255) / 256, 256>>>();
    spectral_kernel<<<B_SZ, 256, SPEC_SMEM_FLOATS * sizeof(float)>>>(byte_ids, fb, w1, b1);
    fused_kernel<<<B_SZ * (T_LEN / 64), 512, FUSED_SMEM_FLOATS * sizeof(float)>>>(
        w1, w2, gamma, beta, b2v, out);
}